// round 13
// baseline (speedup 1.0000x reference)
#include <cuda_runtime.h>

// SSIM loss, single fused kernel, f32x2 packed math.
// pred/target: [16,3,512,512] fp32 -> 48 planes of 512x512.
// Grid: 1536 CTAs x 128 threads (4 warps) = 48 planes x 16 strips x 2 halves.
// Warp = 32-col strip x 64 output rows (74 input rows incl. zero-pad halo).
// Steady loop: 11-row rolled body (I$ ~16KB, under B300 I$ transition),
// single-slot distance-1 LDG prefetch (uniform across rows), runtime-XOR
// double smem buffer, per-row __syncwarp.
// Fields packed as a=p+t, b=p-t:
//   accm = (conv(a), conv(b)), accs = (conv(a^2), conv(b^2))
// Vertical scatter ring: k=0 tap is a MUL into the freshly-consumed slot
// (no ring resets). Ring/weight indices compile-time. Last CTA reduces.

static __device__ double g_partials[1536];
static __device__ unsigned int g_count;   // zero-init; reset by last CTA

__device__ __forceinline__ unsigned long long pk2(float lo, float hi) {
    unsigned long long r;
    asm("mov.b64 %0, {%1, %2};" : "=l"(r) : "f"(lo), "f"(hi));
    return r;
}
__device__ __forceinline__ void up2(unsigned long long v, float& lo, float& hi) {
    asm("mov.b64 {%0, %1}, %2;" : "=f"(lo), "=f"(hi) : "l"(v));
}
__device__ __forceinline__ unsigned long long ffma2(unsigned long long a,
                                                    unsigned long long b,
                                                    unsigned long long c) {
    unsigned long long d;
    asm("fma.rn.f32x2 %0, %1, %2, %3;" : "=l"(d) : "l"(a), "l"(b), "l"(c));
    return d;
}
__device__ __forceinline__ unsigned long long fmul2(unsigned long long a,
                                                    unsigned long long b) {
    unsigned long long d;
    asm("mul.rn.f32x2 %0, %1, %2;" : "=l"(d) : "l"(a), "l"(b));
    return d;
}

// Weight by tap index with symmetry (compile-time select of 6 regs).
#define WT(K) (Wp[(K) < 6 ? (K) : 10 - (K)])

// Single-slot prefetch of input row YY (clamped; zeroed out-of-range rows
// and cols -> matches zero padding). Uniform across rows (no slot parity).
#define PREFETCH1(YY) do {                                                   \
    const int yc = (YY) < 0 ? 0 : ((YY) > 511 ? 511 : (YY));                 \
    const bool rv = ((YY) >= 0) && ((YY) <= 511);                            \
    const float* __restrict__ Prow = P + yc * 512;                           \
    const float* __restrict__ Trow = T + yc * 512;                           \
    if (rv && v0) { pf_p0 = Prow[c0c]; pf_t0 = Trow[c0c]; }                  \
    else          { pf_p0 = 0.0f;      pf_t0 = 0.0f;      }                  \
    if (lane < 10) {                                                         \
        if (rv && v1) { pf_p1 = Prow[c1c]; pf_t1 = Trow[c1c]; }              \
        else          { pf_p1 = 0.0f;      pf_t1 = 0.0f;      }              \
    }                                                                        \
} while (0)

// Stage prefetched row into the current smem buffer (runtime offset).
#define STAGE1() do {                                                        \
    abw[bufoff + lane] = pk2(pf_p0 + pf_t0, pf_p0 - pf_t0);                  \
    if (lane < 10)                                                           \
        abw[bufoff + 32 + lane] = pk2(pf_p1 + pf_t1, pf_p1 - pf_t1);         \
} while (0)

// Horizontal 11-tap pass from current buffer; squares formed on the fly.
#define HPASS1() do {                                                        \
    const unsigned long long* __restrict__ rm = abw + bufoff + lane;         \
    unsigned long long hm0 = 0ull, hm1 = 0ull, hs0 = 0ull, hs1 = 0ull;       \
    _Pragma("unroll")                                                        \
    for (int d = 0; d < 10; d += 2) {                                        \
        const unsigned long long w0 = fmul2(rm[d],     WT(d));               \
        const unsigned long long w1 = fmul2(rm[d + 1], WT(d + 1));           \
        hm0 = ffma2(rm[d],     WT(d),     hm0);                              \
        hm1 = ffma2(rm[d + 1], WT(d + 1), hm1);                              \
        hs0 = ffma2(w0, rm[d],     hs0);                                     \
        hs1 = ffma2(w1, rm[d + 1], hs1);                                     \
    }                                                                        \
    {                                                                        \
        const unsigned long long w = fmul2(rm[10], WT(10));                  \
        hm0 = ffma2(rm[10], WT(10), hm0);                                    \
        hs0 = ffma2(w, rm[10], hs0);                                         \
    }                                                                        \
    {                                                                        \
        float xa, xb, ya, yb;                                                \
        up2(hm0, xa, xb); up2(hm1, ya, yb);                                  \
        hm = pk2(xa + ya, xb + yb);                                          \
        up2(hs0, xa, xb); up2(hs1, ya, yb);                                  \
        hs = pk2(xa + ya, xb + yb);                                          \
    }                                                                        \
} while (0)

// Prologue vertical scatter: taps k = 0..J (slots zero-initialized).
#define VPASS_PRO(J) do {                                                    \
    _Pragma("unroll")                                                        \
    for (int k = 0; k <= (J); ++k) {                                         \
        const int s = ((J) - k + 22) % 11;                                   \
        accm[s] = ffma2(hm, WT(k), accm[s]);                                 \
        accs[s] = ffma2(hs, WT(k), accs[s]);                                 \
    }                                                                        \
} while (0)

// Steady vertical scatter: k=0 writes the freshly-consumed slot (MUL, no
// reset needed); k=1..10 accumulate. UM = j mod 11, compile-time.
#define VPASS_ST(UM) do {                                                    \
    accm[(UM)] = fmul2(hm, WT(0));                                           \
    accs[(UM)] = fmul2(hs, WT(0));                                           \
    _Pragma("unroll")                                                        \
    for (int k = 1; k <= 10; ++k) {                                          \
        const int s = ((UM) - k + 22) % 11;                                  \
        accm[s] = ffma2(hm, WT(k), accm[s]);                                 \
        accs[s] = ffma2(hs, WT(k), accs[s]);                                 \
    }                                                                        \
} while (0)

// Consume a completed output row from ring slot S (no reset).
#define CONSUME(S) do {                                                      \
    float Ma, Mb, Sa, Sb;                                                    \
    up2(accm[(S)], Ma, Mb);                                                  \
    up2(accs[(S)], Sa, Sb);                                                  \
    const float A2 = Ma * Ma, B2 = Mb * Mb;                                  \
    const float dd = 0.5f * (A2 - B2);   /* mu1*mu2         */               \
    const float pq = 0.5f * (A2 + B2);   /* mu1^2 + mu2^2   */               \
    const float q1 = 0.5f * (Sa - Sb);   /* 2*E[pt]         */               \
    const float q2 = 0.5f * (Sa + Sb);   /* E[p^2]+E[t^2]   */               \
    const float num = (dd + C1f) * (q1 - dd + C2f);                          \
    const float den = (pq + C1f) * (q2 - pq + C2f);                          \
    lsum += __fdividef(num, den);                                            \
} while (0)

__global__ __launch_bounds__(128, 4) void ssim_main_kernel(
    const float* __restrict__ pred, const float* __restrict__ target,
    float* __restrict__ out)
{
    constexpr float Wc[6] = {
        0.00102838f, 0.00759876f, 0.03600077f, 0.10936070f, 0.21300553f,
        0.26601212f
    };
    constexpr float C1f = 0.0001f;   // 0.01^2
    constexpr float C2f = 0.0009f;   // 0.03^2

    const int lane  = threadIdx.x & 31;
    const int warp  = threadIdx.x >> 5;
    const int plane = blockIdx.x >> 5;               // 0..47
    const int x0    = ((blockIdx.x >> 1) & 15) << 5; // column tile * 32
    const int half  = blockIdx.x & 1;                // row half (0/1)

    const float* __restrict__ P = pred   + (size_t)plane * (512 * 512);
    const float* __restrict__ T = target + (size_t)plane * (512 * 512);

    const int y0 = half * 256 + (warp << 6);  // first output row (64 rows)
    const int c0 = x0 - 5 + lane;    // staged cols [x0-5, x0+37)
    const int c1 = x0 + 27 + lane;   // extra 10 cols (lanes 0..9)
    const bool v0 = (c0 >= 0) && (c0 < 512);
    const bool v1 = (c1 < 512);
    const int c0c = v0 ? c0 : 0;
    const int c1c = v1 ? c1 : 0;

    __shared__ unsigned long long ab[4][2 * 48];   // double row buffer / warp
    unsigned long long* abw = ab[warp];
    int bufoff = 0;                                // runtime XOR toggle (0/48)

    unsigned long long Wp[6];
#pragma unroll
    for (int i = 0; i < 6; ++i) Wp[i] = pk2(Wc[i], Wc[i]);

    unsigned long long accm[11], accs[11];
#pragma unroll
    for (int s = 0; s < 11; ++s) { accm[s] = 0ull; accs[s] = 0ull; }

    float pf_p0, pf_t0, pf_p1, pf_t1;   // single prefetch slot (distance 1)
    unsigned long long hm, hs;
    float lsum = 0.0f;

    // Prime: prefetch input row for j=0 (global row y0-5).
    PREFETCH1(y0 - 5);

    // ---- Prologue: rows j = 0..10 (compile-time tap counts) ----
#pragma unroll
    for (int j = 0; j <= 10; ++j) {
        STAGE1();
        PREFETCH1(y0 - 4 + j);          // row j+1
        __syncwarp();
        HPASS1();
        bufoff ^= 48;
        VPASS_PRO(j);                    // taps k <= j (slots zero-inited)
        if (j == 10) CONSUME(0);
    }

    // ---- Steady: rows j = 11..73, 11-row rolled body ----
    // jb in {11,22,33,44,55,66}: jb % 11 == 0, so j % 11 == v (compile-time).
    // Last iteration guarded (rows 74..76 skipped); guard is warp-uniform.
    for (int jb = 11; jb <= 66; jb += 11) {
#pragma unroll
        for (int v = 0; v < 11; ++v) {
            const int j = jb + v;
            if (j < 74) {
                STAGE1();
                PREFETCH1(y0 - 4 + j);   // row j+1 (clamped/zeroed past end)
                __syncwarp();
                HPASS1();
                bufoff ^= 48;
                VPASS_ST(v);             // k=0 MUL into fresh slot v
                CONSUME((v + 1) % 11);   // output row j-10
            }
        }
    }

    // ---- Reduce: warp shfl -> CTA smem -> per-CTA partial ----
#pragma unroll
    for (int off = 16; off > 0; off >>= 1)
        lsum += __shfl_xor_sync(0xffffffffu, lsum, off);

    __shared__ float wsum[4];
    if (lane == 0) wsum[warp] = lsum;
    __syncthreads();

    if (threadIdx.x == 0) {
        g_partials[blockIdx.x] =
            (double)wsum[0] + (double)wsum[1] + (double)wsum[2] + (double)wsum[3];
        __threadfence();
        const unsigned int prev = atomicAdd(&g_count, 1u);
        wsum[0] = (prev == 1535u) ? 1.0f : 0.0f;
    }
    __syncthreads();

    // Last CTA reduces all partials and writes the scalar output.
    if (wsum[0] != 0.0f) {
        __threadfence();
        double s = 0.0;
        for (int i = threadIdx.x; i < 1536; i += 128) s += g_partials[i];
        __shared__ double sm[128];
        sm[threadIdx.x] = s;
        __syncthreads();
        for (int off = 64; off > 0; off >>= 1) {
            if (threadIdx.x < off) sm[threadIdx.x] += sm[threadIdx.x + off];
            __syncthreads();
        }
        if (threadIdx.x == 0) {
            out[0] = (float)(1.0 - sm[0] * (1.0 / 12582912.0));
            g_count = 0u;   // reset for next graph replay
        }
    }
}

extern "C" void kernel_launch(void* const* d_in, const int* in_sizes, int n_in,
                              void* d_out, int out_size) {
    const float* pred   = (const float*)d_in[0];
    const float* target = (const float*)d_in[1];
    float* out = (float*)d_out;
    (void)in_sizes; (void)n_in; (void)out_size;

    ssim_main_kernel<<<1536, 128>>>(pred, target, out);
}

// round 15
// speedup vs baseline: 1.1898x; 1.1898x over previous
#include <cuda_runtime.h>

// SSIM loss, single fused kernel, f32x2 packed math, 2-row LDG prefetch.
// (R9 structure, proven 90.6us, + slot-reducing micro-opts: k0-MUL ring
//  writes w/o resets, packed f32x2 accumulator combines.)
// pred/target: [16,3,512,512] fp32 -> 48 planes of 512x512.
// Grid: 1536 CTAs x 128 threads (4 warps) = 48 planes x 16 strips x 2 halves.
// Warp = 32-col strip x 64 output rows (74 input rows incl. halo).
// Fields packed as a=p+t, b=p-t:
//   accm = (conv(a), conv(b)), accs = (conv(a^2), conv(b^2))
// smem stages only the (a,b) row; squares formed on the fly in HPASS.
// Vertical conv scatters into an 11-deep packed register ring; slot s is
// first written by row j==s (mod 11) via its k=0 tap as a MUL -> no init,
// no resets. All register-array indices compile-time. Last CTA reduces.

static __device__ double g_partials[1536];
static __device__ unsigned int g_count;   // zero-init; reset by last CTA

__device__ __forceinline__ unsigned long long pk2(float lo, float hi) {
    unsigned long long r;
    asm("mov.b64 %0, {%1, %2};" : "=l"(r) : "f"(lo), "f"(hi));
    return r;
}
__device__ __forceinline__ void up2(unsigned long long v, float& lo, float& hi) {
    asm("mov.b64 {%0, %1}, %2;" : "=f"(lo), "=f"(hi) : "l"(v));
}
__device__ __forceinline__ unsigned long long ffma2(unsigned long long a,
                                                    unsigned long long b,
                                                    unsigned long long c) {
    unsigned long long d;
    asm("fma.rn.f32x2 %0, %1, %2, %3;" : "=l"(d) : "l"(a), "l"(b), "l"(c));
    return d;
}
__device__ __forceinline__ unsigned long long fmul2(unsigned long long a,
                                                    unsigned long long b) {
    unsigned long long d;
    asm("mul.rn.f32x2 %0, %1, %2;" : "=l"(d) : "l"(a), "l"(b));
    return d;
}
__device__ __forceinline__ unsigned long long fadd2(unsigned long long a,
                                                    unsigned long long b) {
    unsigned long long d;
    asm("add.rn.f32x2 %0, %1, %2;" : "=l"(d) : "l"(a), "l"(b));
    return d;
}

// Weight by tap index with symmetry (compile-time select of 6 regs).
#define WT(K) (Wp[(K) < 6 ? (K) : 10 - (K)])

// Global loads for input row YY into prefetch regs (clamped address, zeroed
// out-of-range -> matches zero padding). SLOT compile-time at every site.
#define PREFETCH(SLOT, YY) do {                                              \
    const int yc = (YY) < 0 ? 0 : ((YY) > 511 ? 511 : (YY));                 \
    const bool rv = ((YY) >= 0) && ((YY) <= 511);                            \
    const float* __restrict__ Prow = P + yc * 512;                           \
    const float* __restrict__ Trow = T + yc * 512;                           \
    if (rv && v0) { pf_p0[SLOT] = Prow[c0c]; pf_t0[SLOT] = Trow[c0c]; }      \
    else          { pf_p0[SLOT] = 0.0f;      pf_t0[SLOT] = 0.0f;      }      \
    if (lane < 10) {                                                         \
        if (rv && v1) { pf_p1[SLOT] = Prow[c1c]; pf_t1[SLOT] = Trow[c1c]; }  \
        else          { pf_p1[SLOT] = 0.0f;      pf_t1[SLOT] = 0.0f;      }  \
    }                                                                        \
} while (0)

// Store prefetched row SLOT into smem buffer SLOT: (a,b) only.
#define STAGE(SLOT) do {                                                     \
    const float a0 = pf_p0[SLOT] + pf_t0[SLOT];                              \
    const float b0 = pf_p0[SLOT] - pf_t0[SLOT];                              \
    abw[(SLOT) * 48 + lane] = pk2(a0, b0);                                   \
    if (lane < 10) {                                                         \
        const float a1 = pf_p1[SLOT] + pf_t1[SLOT];                          \
        const float b1 = pf_p1[SLOT] - pf_t1[SLOT];                          \
        abw[(SLOT) * 48 + 32 + lane] = pk2(a1, b1);                          \
    }                                                                        \
} while (0)

// Horizontal 11-tap pass from smem buffer BUF; squares formed on the fly.
// Accumulator combine uses packed add.rn.f32x2 (no unpack/repack).
#define HPASS(BUF) do {                                                      \
    const unsigned long long* __restrict__ rm = abw + (BUF) * 48 + lane;     \
    unsigned long long hm0 = 0ull, hm1 = 0ull, hs0 = 0ull, hs1 = 0ull;       \
    _Pragma("unroll")                                                        \
    for (int d = 0; d < 10; d += 2) {                                        \
        const unsigned long long w0 = fmul2(rm[d],     WT(d));               \
        const unsigned long long w1 = fmul2(rm[d + 1], WT(d + 1));           \
        hm0 = ffma2(rm[d],     WT(d),     hm0);                              \
        hm1 = ffma2(rm[d + 1], WT(d + 1), hm1);                              \
        hs0 = ffma2(w0, rm[d],     hs0);                                     \
        hs1 = ffma2(w1, rm[d + 1], hs1);                                     \
    }                                                                        \
    {                                                                        \
        const unsigned long long w = fmul2(rm[10], WT(10));                  \
        hm0 = ffma2(rm[10], WT(10), hm0);                                    \
        hs0 = ffma2(w, rm[10], hs0);                                         \
    }                                                                        \
    hm = fadd2(hm0, hm1);                                                    \
    hs = fadd2(hs0, hs1);                                                    \
} while (0)

// Vertical scatter, prologue row J (taps k = 0..J). The k=0 tap writes
// slot J as a MUL -- provably the first write to that slot.
#define VPASS_PRO(J) do {                                                    \
    accm[(J)] = fmul2(hm, WT(0));                                            \
    accs[(J)] = fmul2(hs, WT(0));                                            \
    _Pragma("unroll")                                                        \
    for (int k = 1; k <= (J); ++k) {                                         \
        const int s = ((J) - k + 22) % 11;                                   \
        accm[s] = ffma2(hm, WT(k), accm[s]);                                 \
        accs[s] = ffma2(hs, WT(k), accs[s]);                                 \
    }                                                                        \
} while (0)

// Vertical scatter, steady row with UM = j mod 11 (compile-time). k=0 tap
// re-opens the slot consumed at row j-1 (MUL, no reset needed).
#define VPASS_ST(UM) do {                                                    \
    accm[(UM)] = fmul2(hm, WT(0));                                           \
    accs[(UM)] = fmul2(hs, WT(0));                                           \
    _Pragma("unroll")                                                        \
    for (int k = 1; k <= 10; ++k) {                                          \
        const int s = ((UM) - k + 22) % 11;                                  \
        accm[s] = ffma2(hm, WT(k), accm[s]);                                 \
        accs[s] = ffma2(hs, WT(k), accs[s]);                                 \
    }                                                                        \
} while (0)

// Consume a completed output row from ring slot S (no reset).
#define CONSUME(S) do {                                                      \
    float Ma, Mb, Sa, Sb;                                                    \
    up2(accm[(S)], Ma, Mb);                                                  \
    up2(accs[(S)], Sa, Sb);                                                  \
    const float A2 = Ma * Ma, B2 = Mb * Mb;                                  \
    const float dd = 0.5f * (A2 - B2);   /* mu1*mu2         */               \
    const float pq = 0.5f * (A2 + B2);   /* mu1^2 + mu2^2   */               \
    const float q1 = 0.5f * (Sa - Sb);   /* 2*E[pt]         */               \
    const float q2 = 0.5f * (Sa + Sb);   /* E[p^2]+E[t^2]   */               \
    const float num = (dd + C1f) * (q1 - dd + C2f);                          \
    const float den = (pq + C1f) * (q2 - pq + C2f);                          \
    lsum += __fdividef(num, den);                                            \
} while (0)

// Full steady row step. BUF and UM must be compile-time constants.
#define ROWSTEP(BUF, UM, J) do {                                             \
    STAGE(BUF);                                                              \
    PREFETCH(BUF, y0 - 3 + (J));   /* row (J)+2 into freed slot */           \
    __syncwarp();                                                            \
    HPASS(BUF);                                                              \
    VPASS_ST(UM);                                                            \
    CONSUME(((UM) + 1) % 11);                                                \
} while (0)

__global__ __launch_bounds__(128, 4) void ssim_main_kernel(
    const float* __restrict__ pred, const float* __restrict__ target,
    float* __restrict__ out)
{
    constexpr float Wc[6] = {
        0.00102838f, 0.00759876f, 0.03600077f, 0.10936070f, 0.21300553f,
        0.26601212f
    };
    constexpr float C1f = 0.0001f;   // 0.01^2
    constexpr float C2f = 0.0009f;   // 0.03^2

    const int lane  = threadIdx.x & 31;
    const int warp  = threadIdx.x >> 5;
    const int plane = blockIdx.x >> 5;               // 0..47
    const int x0    = ((blockIdx.x >> 1) & 15) << 5; // column tile * 32
    const int half  = blockIdx.x & 1;                // row half (0/1)

    const float* __restrict__ P = pred   + (size_t)plane * (512 * 512);
    const float* __restrict__ T = target + (size_t)plane * (512 * 512);

    const int y0 = half * 256 + (warp << 6);  // first output row (64 rows)
    const int c0 = x0 - 5 + lane;    // staged cols [x0-5, x0+37)
    const int c1 = x0 + 27 + lane;   // extra 10 cols (lanes 0..9)
    const bool v0 = (c0 >= 0) && (c0 < 512);
    const bool v1 = (c1 < 512);
    const int c0c = v0 ? c0 : 0;
    const int c1c = v1 ? c1 : 0;

    __shared__ unsigned long long ab[4][2 * 48];
    unsigned long long* abw = ab[warp];

    unsigned long long Wp[6];
#pragma unroll
    for (int i = 0; i < 6; ++i) Wp[i] = pk2(Wc[i], Wc[i]);

    unsigned long long accm[11], accs[11];   // no init needed: k0-MUL opens slots

    float pf_p0[2], pf_t0[2], pf_p1[2], pf_t1[2];
    unsigned long long hm, hs;
    float lsum = 0.0f;

    // Prime prefetch: rows j=0,1 (input rows y0-5, y0-4).
    PREFETCH(0, y0 - 5);
    PREFETCH(1, y0 - 4);

    // ---- Prologue: rows j = 0..10 (compile-time tap counts) ----
#pragma unroll
    for (int j = 0; j <= 10; ++j) {
        STAGE(j & 1);
        PREFETCH(j & 1, y0 - 3 + j);   // row j+2
        __syncwarp();
        HPASS(j & 1);
        VPASS_PRO(j);                   // k=0 MUL opens slot j; k<=j taps
        if (j == 10) CONSUME(0);
    }

    // ---- Steady: rows j = 11..54 in two 22-row blocks ----
    // jbb in {11,33}: odd and multiple of 11, so for j = jbb + v:
    //   j & 1    = (v + 1) & 1   (compile-time)
    //   j mod 11 = v mod 11      (compile-time)
    for (int jbb = 11; jbb <= 33; jbb += 22) {
#pragma unroll
        for (int v = 0; v < 22; ++v) {
            ROWSTEP((v + 1) & 1, v % 11, jbb + v);
        }
    }

    // ---- Tail: rows j = 55..73, fully compile-time (55 % 11 == 0) ----
    // Bottom halo rows (yy > 511) stage as zeros via PREFETCH clamp.
#pragma unroll
    for (int j = 55; j <= 73; ++j) {
        ROWSTEP(j & 1, (j - 55) % 11, j);
    }

    // ---- Reduce: warp shfl -> CTA smem -> per-CTA partial ----
#pragma unroll
    for (int off = 16; off > 0; off >>= 1)
        lsum += __shfl_xor_sync(0xffffffffu, lsum, off);

    __shared__ float wsum[4];
    if (lane == 0) wsum[warp] = lsum;
    __syncthreads();

    if (threadIdx.x == 0) {
        g_partials[blockIdx.x] =
            (double)wsum[0] + (double)wsum[1] + (double)wsum[2] + (double)wsum[3];
        __threadfence();
        const unsigned int prev = atomicAdd(&g_count, 1u);
        wsum[0] = (prev == 1535u) ? 1.0f : 0.0f;
    }
    __syncthreads();

    // Last CTA reduces all partials and writes the scalar output.
    if (wsum[0] != 0.0f) {
        __threadfence();
        double s = 0.0;
        for (int i = threadIdx.x; i < 1536; i += 128) s += g_partials[i];
        __shared__ double sm[128];
        sm[threadIdx.x] = s;
        __syncthreads();
        for (int off = 64; off > 0; off >>= 1) {
            if (threadIdx.x < off) sm[threadIdx.x] += sm[threadIdx.x + off];
            __syncthreads();
        }
        if (threadIdx.x == 0) {
            out[0] = (float)(1.0 - sm[0] * (1.0 / 12582912.0));
            g_count = 0u;   // reset for next graph replay
        }
    }
}

extern "C" void kernel_launch(void* const* d_in, const int* in_sizes, int n_in,
                              void* d_out, int out_size) {
    const float* pred   = (const float*)d_in[0];
    const float* target = (const float*)d_in[1];
    float* out = (float*)d_out;
    (void)in_sizes; (void)n_in; (void)out_size;

    ssim_main_kernel<<<1536, 128>>>(pred, target, out);
}